// round 14
// baseline (speedup 1.0000x reference)
#include <cuda_runtime.h>
#include <cuda_fp16.h>
#include <float.h>
#include <stdint.h>

#define N_NODES 8192
#define F_IN    256
#define F_OUT   128
#define KSPLIT  2

// ---------------- scratch (allocation-free: device globals) ----------------
__device__ __half g_h16 [N_NODES * F_OUT];
__device__ float  g_F1  [N_NODES];
__device__ float  g_F2  [N_NODES];
__device__ float  g_E1  [N_NODES];
__device__ float  g_E2  [N_NODES];
__device__ float  g_part[KSPLIT * N_NODES * F_OUT];
__device__ float  g_zp  [KSPLIT * N_NODES];

// ---------------- PTX helpers (baseline, sm_80+) ---------------------------
__device__ __forceinline__ void ldsm_x4(uint32_t* r, uint32_t addr) {
    asm volatile("ldmatrix.sync.aligned.m8n8.x4.shared.b16 {%0,%1,%2,%3}, [%4];"
                 : "=r"(r[0]), "=r"(r[1]), "=r"(r[2]), "=r"(r[3]) : "r"(addr));
}
__device__ __forceinline__ void ldsm_x4_t(uint32_t* r, uint32_t addr) {
    asm volatile("ldmatrix.sync.aligned.m8n8.x4.trans.shared.b16 {%0,%1,%2,%3}, [%4];"
                 : "=r"(r[0]), "=r"(r[1]), "=r"(r[2]), "=r"(r[3]) : "r"(addr));
}
__device__ __forceinline__ void mma16816(float* c, const uint32_t* a,
                                         uint32_t b0, uint32_t b1) {
    asm volatile(
        "mma.sync.aligned.m16n8k16.row.col.f32.f16.f16.f32 "
        "{%0,%1,%2,%3}, {%4,%5,%6,%7}, {%8,%9}, {%0,%1,%2,%3};"
        : "+f"(c[0]), "+f"(c[1]), "+f"(c[2]), "+f"(c[3])
        : "r"(a[0]), "r"(a[1]), "r"(a[2]), "r"(a[3]), "r"(b0), "r"(b1));
}
__device__ __forceinline__ void cp_async16(uint32_t dst, const void* src) {
    asm volatile("cp.async.cg.shared.global [%0], [%1], 16;" :: "r"(dst), "l"(src));
}
#define CP_COMMIT() asm volatile("cp.async.commit_group;" ::: "memory")
#define CP_WAIT0()  asm volatile("cp.async.wait_group 0;" ::: "memory")

// -------- kernel 1: h16 = fp16(x)@fp16(W) (HMMA), conversion fused --------
#define GB_BM 128
#define GB_BK 64
#define GB_NCH (F_IN / GB_BK)
#define XS_STRIDE 72
#define WS_STRIDE 136
#define XS_BUF (GB_BM * XS_STRIDE)
#define SMEM_GH (F_IN * WS_STRIDE * 2 + 2 * XS_BUF * 2)

__global__ void __launch_bounds__(256, 1) k_gemm_h(const float* __restrict__ x,
                                                   const float* __restrict__ W,
                                                   const float* __restrict__ a,
                                                   __half* __restrict__ h16,
                                                   float* __restrict__ F1,
                                                   float* __restrict__ F2,
                                                   float* __restrict__ E1,
                                                   float* __restrict__ E2) {
    extern __shared__ char smem[];
    __half* Ws = (__half*)smem;
    __half* Xs = (__half*)(smem + F_IN * WS_STRIDE * 2);

    const int tid  = threadIdx.x;
    const int wid  = tid >> 5;
    const int lane = tid & 31;
    const int rowBase = blockIdx.x * GB_BM;

    const uint32_t wsBase = (uint32_t)__cvta_generic_to_shared(Ws);
    const uint32_t xsBase = (uint32_t)__cvta_generic_to_shared(Xs);
    const uint32_t aAddr0 = xsBase + (uint32_t)((wid * 16 + (lane & 15)) * (XS_STRIDE * 2))
                                   + (uint32_t)((lane >> 4) * 16);

    auto ldX = [&](float4* xr, int c) {
#pragma unroll
        for (int i = 0; i < 8; i++) {
            int idx = tid + i * 256;
            int r = idx >> 4;
            int g = idx & 15;
            xr[i] = *(const float4*)&x[(size_t)(rowBase + r) * F_IN + c * GB_BK + g * 4];
        }
    };
    auto stX = [&](const float4* xr, int buf) {
        __half* xb = Xs + buf * XS_BUF;
#pragma unroll
        for (int i = 0; i < 8; i++) {
            int idx = tid + i * 256;
            int r = idx >> 4;
            int g = idx & 15;
            __half2 p01 = __floats2half2_rn(xr[i].x, xr[i].y);
            __half2 p23 = __floats2half2_rn(xr[i].z, xr[i].w);
            uint2 hv;
            hv.x = *reinterpret_cast<uint32_t*>(&p01);
            hv.y = *reinterpret_cast<uint32_t*>(&p23);
            *reinterpret_cast<uint2*>(&xb[r * XS_STRIDE + g * 4]) = hv;
        }
    };

    float4 xr[8];
    ldX(xr, 0);                    // in flight while W converts below

#pragma unroll 4
    for (int i = 0; i < 32; i++) {
        int idx = tid + i * 256;
        int r = idx >> 5;
        int g = idx & 31;
        float4 v = *(const float4*)&W[r * F_OUT + g * 4];
        __half2 p01 = __floats2half2_rn(v.x, v.y);
        __half2 p23 = __floats2half2_rn(v.z, v.w);
        uint2 hv;
        hv.x = *reinterpret_cast<uint32_t*>(&p01);
        hv.y = *reinterpret_cast<uint32_t*>(&p23);
        *reinterpret_cast<uint2*>(&Ws[r * WS_STRIDE + g * 4]) = hv;
    }

    float acc[16][4];
#pragma unroll
    for (int i = 0; i < 16; i++)
#pragma unroll
        for (int j = 0; j < 4; j++) acc[i][j] = 0.f;

    stX(xr, 0);
    __syncthreads();

    for (int c = 0; c < GB_NCH; c++) {
        const int cb = c & 1;
        const bool pre = (c + 1 < GB_NCH);
        if (pre) ldX(xr, c + 1);
        const uint32_t psB = aAddr0 + (uint32_t)(cb * XS_BUF * 2);
#pragma unroll
        for (int kt = 0; kt < 4; kt++) {
            uint32_t afr[4];
            ldsm_x4(afr, psB + kt * 32);
            const uint32_t bRowAddr = wsBase
                + (uint32_t)((c * GB_BK + kt * 16 + (lane & 15)) * (WS_STRIDE * 2))
                + (uint32_t)((lane >> 4) * 16);
#pragma unroll
            for (int np = 0; np < 8; np++) {
                uint32_t b[4];
                ldsm_x4_t(b, bRowAddr + np * 32);
                mma16816(acc[np * 2 + 0], afr, b[0], b[1]);
                mma16816(acc[np * 2 + 1], afr, b[2], b[3]);
            }
        }
        if (pre) stX(xr, cb ^ 1);
        __syncthreads();
    }

    const int r0 = rowBase + wid * 16 + (lane >> 2);
    const int c0 = (lane & 3) * 2;
    float s0 = 0.f, t0 = 0.f, s1 = 0.f, t1 = 0.f;
#pragma unroll
    for (int nt = 0; nt < 16; nt++) {
        const int col = nt * 8 + c0;
        __half2 hv0 = __floats2half2_rn(acc[nt][0], acc[nt][1]);
        __half2 hv1 = __floats2half2_rn(acc[nt][2], acc[nt][3]);
        *reinterpret_cast<__half2*>(&h16[(size_t)r0 * F_OUT + col]) = hv0;
        *reinterpret_cast<__half2*>(&h16[(size_t)(r0 + 8) * F_OUT + col]) = hv1;
        float a1x = a[col], a1y = a[col + 1];
        float a2x = a[F_OUT + col], a2y = a[F_OUT + col + 1];
        s0 += acc[nt][0] * a1x + acc[nt][1] * a1y;
        t0 += acc[nt][0] * a2x + acc[nt][1] * a2y;
        s1 += acc[nt][2] * a1x + acc[nt][3] * a1y;
        t1 += acc[nt][2] * a2x + acc[nt][3] * a2y;
    }
#pragma unroll
    for (int off = 1; off <= 2; off <<= 1) {
        s0 += __shfl_xor_sync(0xffffffffu, s0, off);
        t0 += __shfl_xor_sync(0xffffffffu, t0, off);
        s1 += __shfl_xor_sync(0xffffffffu, s1, off);
        t1 += __shfl_xor_sync(0xffffffffu, t1, off);
    }
    if ((lane & 3) == 0) {
        F1[r0] = __expf(s0 - 4.0f);
        F2[r0] = __expf(0.2f * s0 - 4.0f);
        E1[r0] = __expf(t0 - 4.0f);
        E2[r0] = __expf(0.2f * t0 - 4.0f);
        F1[r0 + 8] = __expf(s1 - 4.0f);
        F2[r0 + 8] = __expf(0.2f * s1 - 4.0f);
        E1[r0 + 8] = __expf(t1 - 4.0f);
        E2[r0 + 8] = __expf(0.2f * t1 - 4.0f);
    }
}

// ---------------- kernel 2: fused P + P@H (HMMA), BM=64, occ 3 -------------
// grid = 256: (bid>>1) = 64-row block, (bid&1) = K half (4096 cols).
// Warp tile m16n64 (4M x 2N). ~80 regs, 53 KB smem -> 3 CTAs/SM.
#define BK     64
#define KCOLS  (N_NODES / KSPLIT)     // 4096
#define NCHUNK (KCOLS / BK)           // 64
#define AV_BM  64
#define PS_STRIDE 72
#define HS_STRIDE 136
#define PS_BUF (AV_BM * PS_STRIDE)
#define HS_BUF (BK * HS_STRIDE)
#define SMEM_AV (2 * PS_BUF * 2 + 2 * HS_BUF * 2)

__global__ void __launch_bounds__(256, 3) k_av_mma(const int* __restrict__ adj,
                                                   const __half* __restrict__ h16,
                                                   const float* __restrict__ F1,
                                                   const float* __restrict__ F2,
                                                   const float* __restrict__ E1,
                                                   const float* __restrict__ E2,
                                                   float* __restrict__ part,
                                                   float* __restrict__ zp) {
    extern __shared__ char smem[];
    __half* Ps = (__half*)smem;                      // [2][PS_BUF]
    __half* Hs = (__half*)(smem + 2 * PS_BUF * 2);   // [2][HS_BUF]

    const int tid  = threadIdx.x;
    const int wid  = tid >> 5;
    const int lane = tid & 31;
    const int mw   = wid & 3;          // m16 slice
    const int nw   = wid >> 2;         // n64 slice
    const int rowBase = (blockIdx.x >> 1) * AV_BM;
    const int kh      = blockIdx.x & 1;
    const int jBase   = kh * KCOLS;

    const int jc   = (lane & 15) * 4;
    const int rsub = lane >> 4;

    // per-thread row factors in registers (4 fill passes, rows fixed)
    float f1r[4], f2r[4];
#pragma unroll
    for (int p = 0; p < 4; p++) {
        int r = rowBase + wid * 8 + p * 2 + rsub;
        f1r[p] = F1[r];
        f2r[p] = F2[r];
    }

    const uint32_t psBase = (uint32_t)__cvta_generic_to_shared(Ps);
    const uint32_t hsBase = (uint32_t)__cvta_generic_to_shared(Hs);
    const uint32_t aAddr0 = psBase + (uint32_t)((mw * 16 + (lane & 15)) * (PS_STRIDE * 2))
                                   + (uint32_t)((lane >> 4) * 16);

    float acc[8][4];
#pragma unroll
    for (int i = 0; i < 8; i++)
#pragma unroll
        for (int j = 0; j < 4; j++) acc[i][j] = 0.f;
    float z[4];
#pragma unroll
    for (int p = 0; p < 4; p++) z[p] = 0.f;

    auto ldA4 = [&](int4* av, int c) {
        const int j0 = jBase + c * BK;
#pragma unroll
        for (int p = 0; p < 4; p++) {
            const int row = wid * 8 + p * 2 + rsub;
            av[p] = *(const int4*)&adj[(size_t)(rowBase + row) * N_NODES + j0 + jc];
        }
    };
    auto convP4 = [&](const int4* av, int buf, float4 e1v, float4 e2v) {
        __half* pb = Ps + buf * PS_BUF;
#pragma unroll
        for (int p = 0; p < 4; p++) {
            const int row = wid * 8 + p * 2 + rsub;
            const float f1 = f1r[p];
            const float f2 = f2r[p];
            float p0 = fmaxf(f1 * e1v.x, f2 * e2v.x);
            float p1 = fmaxf(f1 * e1v.y, f2 * e2v.y);
            float p2 = fmaxf(f1 * e1v.z, f2 * e2v.z);
            float p3 = fmaxf(f1 * e1v.w, f2 * e2v.w);
            p0 = (av[p].x > 0) ? p0 : 0.f;
            p1 = (av[p].y > 0) ? p1 : 0.f;
            p2 = (av[p].z > 0) ? p2 : 0.f;
            p3 = (av[p].w > 0) ? p3 : 0.f;
            z[p] += (p0 + p1) + (p2 + p3);
            __half2 h01 = __floats2half2_rn(p0, p1);
            __half2 h23 = __floats2half2_rn(p2, p3);
            uint2 stv;
            stv.x = *reinterpret_cast<uint32_t*>(&h01);
            stv.y = *reinterpret_cast<uint32_t*>(&h23);
            *reinterpret_cast<uint2*>(pb + row * PS_STRIDE + jc) = stv;
        }
    };
    auto fillH_async = [&](int c, int buf) {
        const int j0 = jBase + c * BK;
        const uint32_t hb = hsBase + (uint32_t)(buf * HS_BUF * 2);
#pragma unroll
        for (int i = 0; i < 4; i++) {
            int idx = tid + i * 256;
            int r = idx >> 4;
            int g = idx & 15;
            cp_async16(hb + (uint32_t)(r * (HS_STRIDE * 2) + g * 16),
                       (const char*)(h16 + (size_t)(j0 + r) * F_OUT) + g * 16);
        }
    };
    auto mma2 = [&](int ktBase, int buf) {
        const uint32_t psB = aAddr0 + (uint32_t)(buf * PS_BUF * 2);
        const uint32_t hsB = hsBase + (uint32_t)(buf * HS_BUF * 2);
#pragma unroll
        for (int kt = ktBase; kt < ktBase + 2; kt++) {
            uint32_t afr[4];
            ldsm_x4(afr, psB + kt * 32);
            const uint32_t bRowAddr = hsB
                + (uint32_t)((kt * 16 + (lane & 15)) * (HS_STRIDE * 2))
                + (uint32_t)((lane >> 4) * 16)
                + (uint32_t)(nw * 128);        // n64 slice = 64 halves = 128 B
#pragma unroll
            for (int np = 0; np < 4; np++) {
                uint32_t b[4];
                ldsm_x4_t(b, bRowAddr + np * 32);
                mma16816(acc[np * 2 + 0], afr, b[0], b[1]);
                mma16816(acc[np * 2 + 1], afr, b[2], b[3]);
            }
        }
    };

    // ---- prologue: chunk 0 -> buf 0 ----
    {
        fillH_async(0, 0);
        CP_COMMIT();
        float4 e1v = *(const float4*)&E1[jBase + jc];
        float4 e2v = *(const float4*)&E2[jBase + jc];
        int4 av[4];
        ldA4(av, 0);
        convP4(av, 0, e1v, e2v);
        CP_WAIT0();
    }
    __syncthreads();

    for (int c = 0; c < NCHUNK; c++) {
        const int cb = c & 1;
        const int nb = cb ^ 1;
        const bool pre = (c + 1 < NCHUNK);
        float4 e1n, e2n;
        int4 av[4];
        if (pre) {
            fillH_async(c + 1, nb);
            CP_COMMIT();
            const int j0 = jBase + (c + 1) * BK;
            e1n = *(const float4*)&E1[j0 + jc];
            e2n = *(const float4*)&E2[j0 + jc];
            ldA4(av, c + 1);
        }
        mma2(0, cb);
        if (pre) convP4(av, nb, e1n, e2n);
        mma2(2, cb);
        if (pre) CP_WAIT0();
        __syncthreads();
    }

    // ---- Z partials (16-lane groups) ----
#pragma unroll
    for (int p = 0; p < 4; p++) {
        float zz = z[p];
        zz += __shfl_xor_sync(0xffffffffu, zz, 1);
        zz += __shfl_xor_sync(0xffffffffu, zz, 2);
        zz += __shfl_xor_sync(0xffffffffu, zz, 4);
        zz += __shfl_xor_sync(0xffffffffu, zz, 8);
        if ((lane & 15) == 0)
            zp[kh * N_NODES + rowBase + wid * 8 + p * 2 + rsub] = zz;
    }

    // ---- numerator partials: warp owns rows mw*16..+15, cols nw*64..+63 ----
    float* partOut = part + (size_t)kh * N_NODES * F_OUT;
    const int r0 = rowBase + mw * 16 + (lane >> 2);
    const int c0 = nw * 64 + (lane & 3) * 2;
#pragma unroll
    for (int nt = 0; nt < 8; nt++) {
        const int col = c0 + nt * 8;
        *(float2*)&partOut[(size_t)r0 * F_OUT + col] =
            make_float2(acc[nt][0], acc[nt][1]);
        *(float2*)&partOut[(size_t)(r0 + 8) * F_OUT + col] =
            make_float2(acc[nt][2], acc[nt][3]);
    }
}

// ---------------- kernel 3: out = sum(parts) / sum(z), 8 floats/thread -----
__global__ void __launch_bounds__(256) k_reduce(const float* __restrict__ part,
                                                const float* __restrict__ zp,
                                                float* __restrict__ out) {
    int base = (blockIdx.x * 256 + threadIdx.x) * 8;
    int row = base / F_OUT;
    float zs = 0.f;
#pragma unroll
    for (int q = 0; q < KSPLIT; q++) zs += zp[q * N_NODES + row];
    float zinv = 1.f / zs;
#pragma unroll
    for (int v = 0; v < 2; v++) {
        int i = base + v * 4;
        float4 acc = *(const float4*)&part[i];
#pragma unroll
        for (int q = 1; q < KSPLIT; q++) {
            float4 b = *(const float4*)&part[(size_t)q * N_NODES * F_OUT + i];
            acc.x += b.x; acc.y += b.y; acc.z += b.z; acc.w += b.w;
        }
        float4 o = make_float4(acc.x * zinv, acc.y * zinv, acc.z * zinv, acc.w * zinv);
        *(float4*)&out[i] = o;
    }
}

// ---------------- launch ----------------
extern "C" void kernel_launch(void* const* d_in, const int* in_sizes, int n_in,
                              void* d_out, int out_size) {
    const float* x   = (const float*)d_in[0];
    const int*   adj = (const int*)  d_in[1];
    const float* W   = (const float*)d_in[2];
    const float* a   = (const float*)d_in[3];
    float* out = (float*)d_out;

    float *F1, *F2, *E1, *E2, *part, *zp;
    __half* h16;
    cudaGetSymbolAddress((void**)&h16,  g_h16);
    cudaGetSymbolAddress((void**)&F1,   g_F1);
    cudaGetSymbolAddress((void**)&F2,   g_F2);
    cudaGetSymbolAddress((void**)&E1,   g_E1);
    cudaGetSymbolAddress((void**)&E2,   g_E2);
    cudaGetSymbolAddress((void**)&part, g_part);
    cudaGetSymbolAddress((void**)&zp,   g_zp);

    cudaFuncSetAttribute(k_gemm_h, cudaFuncAttributeMaxDynamicSharedMemorySize, SMEM_GH);
    cudaFuncSetAttribute(k_av_mma, cudaFuncAttributeMaxDynamicSharedMemorySize, SMEM_AV);

    k_gemm_h <<<N_NODES / GB_BM, 256, SMEM_GH>>>(x, W, a, h16, F1, F2, E1, E2);
    k_av_mma <<<(N_NODES / AV_BM) * KSPLIT, 256, SMEM_AV>>>(adj, h16, F1, F2, E1, E2, part, zp);
    k_reduce <<<N_NODES * F_OUT / 2048, 256>>>(part, zp, out);
}

// round 15
// speedup vs baseline: 1.3808x; 1.3808x over previous
#include <cuda_runtime.h>
#include <cuda_fp16.h>
#include <float.h>
#include <stdint.h>

#define N_NODES 8192
#define F_IN    256
#define F_OUT   128
#define KSPLIT  4

// ---------------- scratch (allocation-free: device globals) ----------------
__device__ __half g_h16 [N_NODES * F_OUT];
__device__ float  g_F1  [N_NODES];
__device__ float  g_F2  [N_NODES];
__device__ float  g_E1  [N_NODES];
__device__ float  g_E2  [N_NODES];
__device__ float  g_part[KSPLIT * N_NODES * F_OUT];
__device__ float  g_zp  [KSPLIT * N_NODES];

// ---------------- PTX helpers (baseline, sm_80+) ---------------------------
__device__ __forceinline__ void ldsm_x4(uint32_t* r, uint32_t addr) {
    asm volatile("ldmatrix.sync.aligned.m8n8.x4.shared.b16 {%0,%1,%2,%3}, [%4];"
                 : "=r"(r[0]), "=r"(r[1]), "=r"(r[2]), "=r"(r[3]) : "r"(addr));
}
__device__ __forceinline__ void ldsm_x4_t(uint32_t* r, uint32_t addr) {
    asm volatile("ldmatrix.sync.aligned.m8n8.x4.trans.shared.b16 {%0,%1,%2,%3}, [%4];"
                 : "=r"(r[0]), "=r"(r[1]), "=r"(r[2]), "=r"(r[3]) : "r"(addr));
}
__device__ __forceinline__ void mma16816(float* c, const uint32_t* a,
                                         uint32_t b0, uint32_t b1) {
    asm volatile(
        "mma.sync.aligned.m16n8k16.row.col.f32.f16.f16.f32 "
        "{%0,%1,%2,%3}, {%4,%5,%6,%7}, {%8,%9}, {%0,%1,%2,%3};"
        : "+f"(c[0]), "+f"(c[1]), "+f"(c[2]), "+f"(c[3])
        : "r"(a[0]), "r"(a[1]), "r"(a[2]), "r"(a[3]), "r"(b0), "r"(b1));
}
__device__ __forceinline__ void cp_async16(uint32_t dst, const void* src) {
    asm volatile("cp.async.cg.shared.global [%0], [%1], 16;" :: "r"(dst), "l"(src));
}
#define CP_COMMIT() asm volatile("cp.async.commit_group;" ::: "memory")
#define CP_WAIT0()  asm volatile("cp.async.wait_group 0;" ::: "memory")

// -------- kernel 1: h16 = fp16(x)@fp16(W) (HMMA), conversion fused --------
#define GB_BM 128
#define GB_BK 64
#define GB_NCH (F_IN / GB_BK)
#define XS_STRIDE 72
#define WS_STRIDE 136
#define XS_BUF (GB_BM * XS_STRIDE)
#define SMEM_GH (F_IN * WS_STRIDE * 2 + 2 * XS_BUF * 2)

__global__ void __launch_bounds__(256, 1) k_gemm_h(const float* __restrict__ x,
                                                   const float* __restrict__ W,
                                                   const float* __restrict__ a,
                                                   __half* __restrict__ h16,
                                                   float* __restrict__ F1,
                                                   float* __restrict__ F2,
                                                   float* __restrict__ E1,
                                                   float* __restrict__ E2) {
    extern __shared__ char smem[];
    __half* Ws = (__half*)smem;
    __half* Xs = (__half*)(smem + F_IN * WS_STRIDE * 2);

    const int tid  = threadIdx.x;
    const int wid  = tid >> 5;
    const int lane = tid & 31;
    const int rowBase = blockIdx.x * GB_BM;

    const uint32_t wsBase = (uint32_t)__cvta_generic_to_shared(Ws);
    const uint32_t xsBase = (uint32_t)__cvta_generic_to_shared(Xs);
    const uint32_t aAddr0 = xsBase + (uint32_t)((wid * 16 + (lane & 15)) * (XS_STRIDE * 2))
                                   + (uint32_t)((lane >> 4) * 16);

    // ---- W fp32 -> fp16 smem (once) ----
#pragma unroll 4
    for (int i = 0; i < 32; i++) {
        int idx = tid + i * 256;           // 8192 float4 granules (256x128 fp32)
        int r = idx >> 5;
        int g = idx & 31;
        float4 v = *(const float4*)&W[r * F_OUT + g * 4];
        __half2 p01 = __floats2half2_rn(v.x, v.y);
        __half2 p23 = __floats2half2_rn(v.z, v.w);
        uint2 hv;
        hv.x = *reinterpret_cast<uint32_t*>(&p01);
        hv.y = *reinterpret_cast<uint32_t*>(&p23);
        *reinterpret_cast<uint2*>(&Ws[r * WS_STRIDE + g * 4]) = hv;
    }

    // ---- X chunk: LDG fp32 -> regs, convert -> STS fp16 ----
    auto ldX = [&](float4* xr, int c) {
#pragma unroll
        for (int i = 0; i < 8; i++) {
            int idx = tid + i * 256;       // 2048 granules (128x64 fp32)
            int r = idx >> 4;
            int g = idx & 15;
            xr[i] = *(const float4*)&x[(size_t)(rowBase + r) * F_IN + c * GB_BK + g * 4];
        }
    };
    auto stX = [&](const float4* xr, int buf) {
        __half* xb = Xs + buf * XS_BUF;
#pragma unroll
        for (int i = 0; i < 8; i++) {
            int idx = tid + i * 256;
            int r = idx >> 4;
            int g = idx & 15;
            __half2 p01 = __floats2half2_rn(xr[i].x, xr[i].y);
            __half2 p23 = __floats2half2_rn(xr[i].z, xr[i].w);
            uint2 hv;
            hv.x = *reinterpret_cast<uint32_t*>(&p01);
            hv.y = *reinterpret_cast<uint32_t*>(&p23);
            *reinterpret_cast<uint2*>(&xb[r * XS_STRIDE + g * 4]) = hv;
        }
    };

    float acc[16][4];
#pragma unroll
    for (int i = 0; i < 16; i++)
#pragma unroll
        for (int j = 0; j < 4; j++) acc[i][j] = 0.f;

    float4 xr[8];
    ldX(xr, 0);
    stX(xr, 0);
    __syncthreads();

    for (int c = 0; c < GB_NCH; c++) {
        const int cb = c & 1;
        const bool pre = (c + 1 < GB_NCH);
        if (pre) ldX(xr, c + 1);
        const uint32_t psB = aAddr0 + (uint32_t)(cb * XS_BUF * 2);
#pragma unroll
        for (int kt = 0; kt < 4; kt++) {
            uint32_t afr[4];
            ldsm_x4(afr, psB + kt * 32);
            const uint32_t bRowAddr = wsBase
                + (uint32_t)((c * GB_BK + kt * 16 + (lane & 15)) * (WS_STRIDE * 2))
                + (uint32_t)((lane >> 4) * 16);
#pragma unroll
            for (int np = 0; np < 8; np++) {
                uint32_t b[4];
                ldsm_x4_t(b, bRowAddr + np * 32);
                mma16816(acc[np * 2 + 0], afr, b[0], b[1]);
                mma16816(acc[np * 2 + 1], afr, b[2], b[3]);
            }
        }
        if (pre) stX(xr, cb ^ 1);
        __syncthreads();
    }

    const int r0 = rowBase + wid * 16 + (lane >> 2);
    const int c0 = (lane & 3) * 2;
    float s0 = 0.f, t0 = 0.f, s1 = 0.f, t1 = 0.f;
#pragma unroll
    for (int nt = 0; nt < 16; nt++) {
        const int col = nt * 8 + c0;
        __half2 hv0 = __floats2half2_rn(acc[nt][0], acc[nt][1]);
        __half2 hv1 = __floats2half2_rn(acc[nt][2], acc[nt][3]);
        *reinterpret_cast<__half2*>(&h16[(size_t)r0 * F_OUT + col]) = hv0;
        *reinterpret_cast<__half2*>(&h16[(size_t)(r0 + 8) * F_OUT + col]) = hv1;
        float a1x = a[col], a1y = a[col + 1];
        float a2x = a[F_OUT + col], a2y = a[F_OUT + col + 1];
        s0 += acc[nt][0] * a1x + acc[nt][1] * a1y;
        t0 += acc[nt][0] * a2x + acc[nt][1] * a2y;
        s1 += acc[nt][2] * a1x + acc[nt][3] * a1y;
        t1 += acc[nt][2] * a2x + acc[nt][3] * a2y;
    }
#pragma unroll
    for (int off = 1; off <= 2; off <<= 1) {
        s0 += __shfl_xor_sync(0xffffffffu, s0, off);
        t0 += __shfl_xor_sync(0xffffffffu, t0, off);
        s1 += __shfl_xor_sync(0xffffffffu, s1, off);
        t1 += __shfl_xor_sync(0xffffffffu, t1, off);
    }
    if ((lane & 3) == 0) {
        F1[r0] = __expf(s0 - 4.0f);
        F2[r0] = __expf(0.2f * s0 - 4.0f);
        E1[r0] = __expf(t0 - 4.0f);
        E2[r0] = __expf(0.2f * t0 - 4.0f);
        F1[r0 + 8] = __expf(s1 - 4.0f);
        F2[r0 + 8] = __expf(0.2f * s1 - 4.0f);
        E1[r0 + 8] = __expf(t1 - 4.0f);
        E2[r0 + 8] = __expf(0.2f * t1 - 4.0f);
    }
}

// ---------------- kernel 2: fused P-compute + P@H (HMMA) + Z ---------------
// (R9/R11 version — best known)
#define BK     64
#define KCOLS  (N_NODES / KSPLIT)
#define NCHUNK (KCOLS / BK)
#define PS_STRIDE 72
#define HS_STRIDE 136
#define PS_BUF (128 * PS_STRIDE)
#define HS_BUF (BK * HS_STRIDE)
#define SMEM_F  (2 * PS_BUF * 2 + 2 * HS_BUF * 2)
#define SMEM_AV (SMEM_F + 2 * 128 * 4)

__global__ void __launch_bounds__(256, 2) k_av_mma(const int* __restrict__ adj,
                                                   const __half* __restrict__ h16,
                                                   const float* __restrict__ F1,
                                                   const float* __restrict__ F2,
                                                   const float* __restrict__ E1,
                                                   const float* __restrict__ E2,
                                                   float* __restrict__ part,
                                                   float* __restrict__ zp) {
    extern __shared__ char smem[];
    __half* Ps  = (__half*)smem;
    __half* Hs  = (__half*)(smem + 2 * PS_BUF * 2);
    float*  sF1 = (float*)(smem + SMEM_F);
    float*  sF2 = sF1 + 128;

    const int tid  = threadIdx.x;
    const int wid  = tid >> 5;
    const int lane = tid & 31;
    const int rowBase = (blockIdx.x >> 2) * 128;
    const int kh      = blockIdx.x & 3;
    const int jBase   = kh * KCOLS;

    if (tid < 128) {
        sF1[tid] = F1[rowBase + tid];
        sF2[tid] = F2[rowBase + tid];
    }

    const int jc   = (lane & 15) * 4;
    const int rsub = lane >> 4;

    const uint32_t psBase = (uint32_t)__cvta_generic_to_shared(Ps);
    const uint32_t hsBase = (uint32_t)__cvta_generic_to_shared(Hs);
    const uint32_t aAddr0 = psBase + (uint32_t)((wid * 16 + (lane & 15)) * (PS_STRIDE * 2))
                                   + (uint32_t)((lane >> 4) * 16);

    float acc[16][4];
#pragma unroll
    for (int i = 0; i < 16; i++)
#pragma unroll
        for (int j = 0; j < 4; j++) acc[i][j] = 0.f;
    float z[8];
#pragma unroll
    for (int p = 0; p < 8; p++) z[p] = 0.f;

    auto ldA4 = [&](int4* av, int pbase, int c) {
        const int j0 = jBase + c * BK;
#pragma unroll
        for (int p = 0; p < 4; p++) {
            const int row = wid * 16 + (pbase + p) * 2 + rsub;
            av[p] = *(const int4*)&adj[(size_t)(rowBase + row) * N_NODES + j0 + jc];
        }
    };
    auto convP4 = [&](const int4* av, int pbase, int buf,
                      float4 e1v, float4 e2v) {
        __half* pb = Ps + buf * PS_BUF;
#pragma unroll
        for (int p = 0; p < 4; p++) {
            const int row = wid * 16 + (pbase + p) * 2 + rsub;
            const float f1 = sF1[row];
            const float f2 = sF2[row];
            float p0 = fmaxf(f1 * e1v.x, f2 * e2v.x);
            float p1 = fmaxf(f1 * e1v.y, f2 * e2v.y);
            float p2 = fmaxf(f1 * e1v.z, f2 * e2v.z);
            float p3 = fmaxf(f1 * e1v.w, f2 * e2v.w);
            p0 = (av[p].x > 0) ? p0 : 0.f;
            p1 = (av[p].y > 0) ? p1 : 0.f;
            p2 = (av[p].z > 0) ? p2 : 0.f;
            p3 = (av[p].w > 0) ? p3 : 0.f;
            z[pbase + p] += (p0 + p1) + (p2 + p3);
            __half2 h01 = __floats2half2_rn(p0, p1);
            __half2 h23 = __floats2half2_rn(p2, p3);
            uint2 stv;
            stv.x = *reinterpret_cast<uint32_t*>(&h01);
            stv.y = *reinterpret_cast<uint32_t*>(&h23);
            *reinterpret_cast<uint2*>(pb + row * PS_STRIDE + jc) = stv;
        }
    };
    auto fillH_async = [&](int c, int buf) {
        const int j0 = jBase + c * BK;
        const uint32_t hb = hsBase + (uint32_t)(buf * HS_BUF * 2);
#pragma unroll
        for (int i = 0; i < 4; i++) {
            int idx = tid + i * 256;
            int r = idx >> 4;
            int g = idx & 15;
            cp_async16(hb + (uint32_t)(r * (HS_STRIDE * 2) + g * 16),
                       (const char*)(h16 + (size_t)(j0 + r) * F_OUT) + g * 16);
        }
    };
    auto mma2 = [&](int ktBase, int buf) {
        const uint32_t psB = aAddr0 + (uint32_t)(buf * PS_BUF * 2);
        const uint32_t hsB = hsBase + (uint32_t)(buf * HS_BUF * 2);
#pragma unroll
        for (int kt = ktBase; kt < ktBase + 2; kt++) {
            uint32_t afr[4];
            ldsm_x4(afr, psB + kt * 32);
            const uint32_t bRowAddr = hsB
                + (uint32_t)((kt * 16 + (lane & 15)) * (HS_STRIDE * 2))
                + (uint32_t)((lane >> 4) * 16);
#pragma unroll
            for (int np = 0; np < 8; np++) {
                uint32_t b[4];
                ldsm_x4_t(b, bRowAddr + np * 32);
                mma16816(acc[np * 2 + 0], afr, b[0], b[1]);
                mma16816(acc[np * 2 + 1], afr, b[2], b[3]);
            }
        }
    };

    __syncthreads();

    {
        fillH_async(0, 0);
        CP_COMMIT();
        const int j0 = jBase;
        float4 e1v = *(const float4*)&E1[j0 + jc];
        float4 e2v = *(const float4*)&E2[j0 + jc];
        int4 avA[4], avB[4];
        ldA4(avA, 0, 0);
        ldA4(avB, 4, 0);
        convP4(avA, 0, 0, e1v, e2v);
        convP4(avB, 4, 0, e1v, e2v);
        CP_WAIT0();
    }
    __syncthreads();

    for (int c = 0; c < NCHUNK; c++) {
        const int cb = c & 1;
        const int nb = cb ^ 1;
        const bool pre = (c + 1 < NCHUNK);
        float4 e1n, e2n;
        int4 avA[4], avB[4];
        if (pre) {
            fillH_async(c + 1, nb);
            CP_COMMIT();
            const int j0 = jBase + (c + 1) * BK;
            e1n = *(const float4*)&E1[j0 + jc];
            e2n = *(const float4*)&E2[j0 + jc];
            ldA4(avA, 0, c + 1);
        }
        mma2(0, cb);
        if (pre) {
            convP4(avA, 0, nb, e1n, e2n);
            ldA4(avB, 4, c + 1);
        }
        mma2(2, cb);
        if (pre) {
            convP4(avB, 4, nb, e1n, e2n);
            CP_WAIT0();
        }
        __syncthreads();
    }

#pragma unroll
    for (int p = 0; p < 8; p++) {
        float zz = z[p];
        zz += __shfl_xor_sync(0xffffffffu, zz, 1);
        zz += __shfl_xor_sync(0xffffffffu, zz, 2);
        zz += __shfl_xor_sync(0xffffffffu, zz, 4);
        zz += __shfl_xor_sync(0xffffffffu, zz, 8);
        if ((lane & 15) == 0)
            zp[kh * N_NODES + rowBase + wid * 16 + p * 2 + rsub] = zz;
    }

    float* partOut = part + (size_t)kh * N_NODES * F_OUT;
    const int r0 = rowBase + wid * 16 + (lane >> 2);
    const int c0 = (lane & 3) * 2;
#pragma unroll
    for (int nt = 0; nt < 16; nt++) {
        *(float2*)&partOut[(size_t)r0 * F_OUT + nt * 8 + c0] =
            make_float2(acc[nt][0], acc[nt][1]);
        *(float2*)&partOut[(size_t)(r0 + 8) * F_OUT + nt * 8 + c0] =
            make_float2(acc[nt][2], acc[nt][3]);
    }
}

// ---------------- kernel 3: out = sum(parts) / sum(z), 8 floats/thread -----
__global__ void __launch_bounds__(256) k_reduce(const float* __restrict__ part,
                                                const float* __restrict__ zp,
                                                float* __restrict__ out) {
    int base = (blockIdx.x * 256 + threadIdx.x) * 8;
    int row = base / F_OUT;
    float zs = 0.f;
#pragma unroll
    for (int q = 0; q < KSPLIT; q++) zs += zp[q * N_NODES + row];
    float zinv = 1.f / zs;
#pragma unroll
    for (int v = 0; v < 2; v++) {
        int i = base + v * 4;
        float4 acc = *(const float4*)&part[i];
#pragma unroll
        for (int q = 1; q < KSPLIT; q++) {
            float4 b = *(const float4*)&part[(size_t)q * N_NODES * F_OUT + i];
            acc.x += b.x; acc.y += b.y; acc.z += b.z; acc.w += b.w;
        }
        float4 o = make_float4(acc.x * zinv, acc.y * zinv, acc.z * zinv, acc.w * zinv);
        *(float4*)&out[i] = o;
    }
}

// ---------------- launch ----------------
extern "C" void kernel_launch(void* const* d_in, const int* in_sizes, int n_in,
                              void* d_out, int out_size) {
    const float* x   = (const float*)d_in[0];
    const int*   adj = (const int*)  d_in[1];
    const float* W   = (const float*)d_in[2];
    const float* a   = (const float*)d_in[3];
    float* out = (float*)d_out;

    float *F1, *F2, *E1, *E2, *part, *zp;
    __half* h16;
    cudaGetSymbolAddress((void**)&h16,  g_h16);
    cudaGetSymbolAddress((void**)&F1,   g_F1);
    cudaGetSymbolAddress((void**)&F2,   g_F2);
    cudaGetSymbolAddress((void**)&E1,   g_E1);
    cudaGetSymbolAddress((void**)&E2,   g_E2);
    cudaGetSymbolAddress((void**)&part, g_part);
    cudaGetSymbolAddress((void**)&zp,   g_zp);

    cudaFuncSetAttribute(k_gemm_h, cudaFuncAttributeMaxDynamicSharedMemorySize, SMEM_GH);
    cudaFuncSetAttribute(k_av_mma, cudaFuncAttributeMaxDynamicSharedMemorySize, SMEM_AV);

    k_gemm_h <<<N_NODES / GB_BM, 256, SMEM_GH>>>(x, W, a, h16, F1, F2, E1, E2);
    k_av_mma <<<(N_NODES / 128) * KSPLIT, 256, SMEM_AV>>>(adj, h16, F1, F2, E1, E2, part, zp);
    k_reduce <<<N_NODES * F_OUT / 2048, 256>>>(part, zp, out);
}

// round 16
// speedup vs baseline: 1.4302x; 1.0358x over previous
#include <cuda_runtime.h>
#include <cuda_fp16.h>
#include <float.h>
#include <stdint.h>

#define N_NODES 8192
#define F_IN    256
#define F_OUT   128
#define KSPLIT  4

// ---------------- scratch (allocation-free: device globals) ----------------
__device__ __half g_h16 [N_NODES * F_OUT];
__device__ float  g_F1  [N_NODES];
__device__ float  g_F2  [N_NODES];
__device__ float  g_E1  [N_NODES];
__device__ float  g_E2  [N_NODES];
__device__ float  g_part[KSPLIT * N_NODES * F_OUT];
__device__ float  g_zp  [KSPLIT * N_NODES];

// ---------------- PTX helpers (baseline, sm_80+) ---------------------------
__device__ __forceinline__ void ldsm_x4(uint32_t* r, uint32_t addr) {
    asm volatile("ldmatrix.sync.aligned.m8n8.x4.shared.b16 {%0,%1,%2,%3}, [%4];"
                 : "=r"(r[0]), "=r"(r[1]), "=r"(r[2]), "=r"(r[3]) : "r"(addr));
}
__device__ __forceinline__ void ldsm_x4_t(uint32_t* r, uint32_t addr) {
    asm volatile("ldmatrix.sync.aligned.m8n8.x4.trans.shared.b16 {%0,%1,%2,%3}, [%4];"
                 : "=r"(r[0]), "=r"(r[1]), "=r"(r[2]), "=r"(r[3]) : "r"(addr));
}
__device__ __forceinline__ void mma16816(float* c, const uint32_t* a,
                                         uint32_t b0, uint32_t b1) {
    asm volatile(
        "mma.sync.aligned.m16n8k16.row.col.f32.f16.f16.f32 "
        "{%0,%1,%2,%3}, {%4,%5,%6,%7}, {%8,%9}, {%0,%1,%2,%3};"
        : "+f"(c[0]), "+f"(c[1]), "+f"(c[2]), "+f"(c[3])
        : "r"(a[0]), "r"(a[1]), "r"(a[2]), "r"(a[3]), "r"(b0), "r"(b1));
}
__device__ __forceinline__ void cp_async16(uint32_t dst, const void* src) {
    asm volatile("cp.async.cg.shared.global [%0], [%1], 16;" :: "r"(dst), "l"(src));
}
#define CP_COMMIT() asm volatile("cp.async.commit_group;" ::: "memory")
#define CP_WAIT0()  asm volatile("cp.async.wait_group 0;" ::: "memory")

// -------- kernel 1: h16 = fp16(x)@fp16(W) (HMMA), conversion fused --------
#define GB_BM 128
#define GB_BK 64
#define GB_NCH (F_IN / GB_BK)
#define XS_STRIDE 72
#define WS_STRIDE 136
#define XS_BUF (GB_BM * XS_STRIDE)
#define SMEM_GH (F_IN * WS_STRIDE * 2 + 2 * XS_BUF * 2)

__global__ void __launch_bounds__(256, 1) k_gemm_h(const float* __restrict__ x,
                                                   const float* __restrict__ W,
                                                   const float* __restrict__ a,
                                                   __half* __restrict__ h16,
                                                   float* __restrict__ F1,
                                                   float* __restrict__ F2,
                                                   float* __restrict__ E1,
                                                   float* __restrict__ E2) {
    extern __shared__ char smem[];
    __half* Ws = (__half*)smem;
    __half* Xs = (__half*)(smem + F_IN * WS_STRIDE * 2);

    const int tid  = threadIdx.x;
    const int wid  = tid >> 5;
    const int lane = tid & 31;
    const int rowBase = blockIdx.x * GB_BM;

    const uint32_t wsBase = (uint32_t)__cvta_generic_to_shared(Ws);
    const uint32_t xsBase = (uint32_t)__cvta_generic_to_shared(Xs);
    const uint32_t aAddr0 = xsBase + (uint32_t)((wid * 16 + (lane & 15)) * (XS_STRIDE * 2))
                                   + (uint32_t)((lane >> 4) * 16);

    // ---- W fp32 -> fp16 smem (once); FULL unroll batches all 32 LDGs ----
#pragma unroll
    for (int i = 0; i < 32; i++) {
        int idx = tid + i * 256;           // 8192 float4 granules (256x128 fp32)
        int r = idx >> 5;
        int g = idx & 31;
        float4 v = *(const float4*)&W[r * F_OUT + g * 4];
        __half2 p01 = __floats2half2_rn(v.x, v.y);
        __half2 p23 = __floats2half2_rn(v.z, v.w);
        uint2 hv;
        hv.x = *reinterpret_cast<uint32_t*>(&p01);
        hv.y = *reinterpret_cast<uint32_t*>(&p23);
        *reinterpret_cast<uint2*>(&Ws[r * WS_STRIDE + g * 4]) = hv;
    }

    // ---- X chunk: LDG fp32 -> regs, convert -> STS fp16 ----
    auto ldX = [&](float4* xr, int c) {
#pragma unroll
        for (int i = 0; i < 8; i++) {
            int idx = tid + i * 256;       // 2048 granules (128x64 fp32)
            int r = idx >> 4;
            int g = idx & 15;
            xr[i] = *(const float4*)&x[(size_t)(rowBase + r) * F_IN + c * GB_BK + g * 4];
        }
    };
    auto stX = [&](const float4* xr, int buf) {
        __half* xb = Xs + buf * XS_BUF;
#pragma unroll
        for (int i = 0; i < 8; i++) {
            int idx = tid + i * 256;
            int r = idx >> 4;
            int g = idx & 15;
            __half2 p01 = __floats2half2_rn(xr[i].x, xr[i].y);
            __half2 p23 = __floats2half2_rn(xr[i].z, xr[i].w);
            uint2 hv;
            hv.x = *reinterpret_cast<uint32_t*>(&p01);
            hv.y = *reinterpret_cast<uint32_t*>(&p23);
            *reinterpret_cast<uint2*>(&xb[r * XS_STRIDE + g * 4]) = hv;
        }
    };

    float acc[16][4];
#pragma unroll
    for (int i = 0; i < 16; i++)
#pragma unroll
        for (int j = 0; j < 4; j++) acc[i][j] = 0.f;

    float4 xr[8];
    ldX(xr, 0);
    stX(xr, 0);
    __syncthreads();

    for (int c = 0; c < GB_NCH; c++) {
        const int cb = c & 1;
        const bool pre = (c + 1 < GB_NCH);
        if (pre) ldX(xr, c + 1);
        const uint32_t psB = aAddr0 + (uint32_t)(cb * XS_BUF * 2);
#pragma unroll
        for (int kt = 0; kt < 4; kt++) {
            uint32_t afr[4];
            ldsm_x4(afr, psB + kt * 32);
            const uint32_t bRowAddr = wsBase
                + (uint32_t)((c * GB_BK + kt * 16 + (lane & 15)) * (WS_STRIDE * 2))
                + (uint32_t)((lane >> 4) * 16);
#pragma unroll
            for (int np = 0; np < 8; np++) {
                uint32_t b[4];
                ldsm_x4_t(b, bRowAddr + np * 32);
                mma16816(acc[np * 2 + 0], afr, b[0], b[1]);
                mma16816(acc[np * 2 + 1], afr, b[2], b[3]);
            }
        }
        if (pre) stX(xr, cb ^ 1);
        __syncthreads();
    }

    const int r0 = rowBase + wid * 16 + (lane >> 2);
    const int c0 = (lane & 3) * 2;
    float s0 = 0.f, t0 = 0.f, s1 = 0.f, t1 = 0.f;
#pragma unroll
    for (int nt = 0; nt < 16; nt++) {
        const int col = nt * 8 + c0;
        __half2 hv0 = __floats2half2_rn(acc[nt][0], acc[nt][1]);
        __half2 hv1 = __floats2half2_rn(acc[nt][2], acc[nt][3]);
        *reinterpret_cast<__half2*>(&h16[(size_t)r0 * F_OUT + col]) = hv0;
        *reinterpret_cast<__half2*>(&h16[(size_t)(r0 + 8) * F_OUT + col]) = hv1;
        float a1x = a[col], a1y = a[col + 1];
        float a2x = a[F_OUT + col], a2y = a[F_OUT + col + 1];
        s0 += acc[nt][0] * a1x + acc[nt][1] * a1y;
        t0 += acc[nt][0] * a2x + acc[nt][1] * a2y;
        s1 += acc[nt][2] * a1x + acc[nt][3] * a1y;
        t1 += acc[nt][2] * a2x + acc[nt][3] * a2y;
    }
#pragma unroll
    for (int off = 1; off <= 2; off <<= 1) {
        s0 += __shfl_xor_sync(0xffffffffu, s0, off);
        t0 += __shfl_xor_sync(0xffffffffu, t0, off);
        s1 += __shfl_xor_sync(0xffffffffu, s1, off);
        t1 += __shfl_xor_sync(0xffffffffu, t1, off);
    }
    if ((lane & 3) == 0) {
        F1[r0] = __expf(s0 - 4.0f);
        F2[r0] = __expf(0.2f * s0 - 4.0f);
        E1[r0] = __expf(t0 - 4.0f);
        E2[r0] = __expf(0.2f * t0 - 4.0f);
        F1[r0 + 8] = __expf(s1 - 4.0f);
        F2[r0 + 8] = __expf(0.2f * s1 - 4.0f);
        E1[r0 + 8] = __expf(t1 - 4.0f);
        E2[r0 + 8] = __expf(0.2f * t1 - 4.0f);
    }
}

// ---------------- kernel 2: fused P-compute + P@H (HMMA) + Z ---------------
// (R9/R11 version — best known)
#define BK     64
#define KCOLS  (N_NODES / KSPLIT)
#define NCHUNK (KCOLS / BK)
#define PS_STRIDE 72
#define HS_STRIDE 136
#define PS_BUF (128 * PS_STRIDE)
#define HS_BUF (BK * HS_STRIDE)
#define SMEM_F  (2 * PS_BUF * 2 + 2 * HS_BUF * 2)
#define SMEM_AV (SMEM_F + 2 * 128 * 4)

__global__ void __launch_bounds__(256, 2) k_av_mma(const int* __restrict__ adj,
                                                   const __half* __restrict__ h16,
                                                   const float* __restrict__ F1,
                                                   const float* __restrict__ F2,
                                                   const float* __restrict__ E1,
                                                   const float* __restrict__ E2,
                                                   float* __restrict__ part,
                                                   float* __restrict__ zp) {
    extern __shared__ char smem[];
    __half* Ps  = (__half*)smem;
    __half* Hs  = (__half*)(smem + 2 * PS_BUF * 2);
    float*  sF1 = (float*)(smem + SMEM_F);
    float*  sF2 = sF1 + 128;

    const int tid  = threadIdx.x;
    const int wid  = tid >> 5;
    const int lane = tid & 31;
    const int rowBase = (blockIdx.x >> 2) * 128;
    const int kh      = blockIdx.x & 3;
    const int jBase   = kh * KCOLS;

    if (tid < 128) {
        sF1[tid] = F1[rowBase + tid];
        sF2[tid] = F2[rowBase + tid];
    }

    const int jc   = (lane & 15) * 4;
    const int rsub = lane >> 4;

    const uint32_t psBase = (uint32_t)__cvta_generic_to_shared(Ps);
    const uint32_t hsBase = (uint32_t)__cvta_generic_to_shared(Hs);
    const uint32_t aAddr0 = psBase + (uint32_t)((wid * 16 + (lane & 15)) * (PS_STRIDE * 2))
                                   + (uint32_t)((lane >> 4) * 16);

    float acc[16][4];
#pragma unroll
    for (int i = 0; i < 16; i++)
#pragma unroll
        for (int j = 0; j < 4; j++) acc[i][j] = 0.f;
    float z[8];
#pragma unroll
    for (int p = 0; p < 8; p++) z[p] = 0.f;

    auto ldA4 = [&](int4* av, int pbase, int c) {
        const int j0 = jBase + c * BK;
#pragma unroll
        for (int p = 0; p < 4; p++) {
            const int row = wid * 16 + (pbase + p) * 2 + rsub;
            av[p] = *(const int4*)&adj[(size_t)(rowBase + row) * N_NODES + j0 + jc];
        }
    };
    auto convP4 = [&](const int4* av, int pbase, int buf,
                      float4 e1v, float4 e2v) {
        __half* pb = Ps + buf * PS_BUF;
#pragma unroll
        for (int p = 0; p < 4; p++) {
            const int row = wid * 16 + (pbase + p) * 2 + rsub;
            const float f1 = sF1[row];
            const float f2 = sF2[row];
            float p0 = fmaxf(f1 * e1v.x, f2 * e2v.x);
            float p1 = fmaxf(f1 * e1v.y, f2 * e2v.y);
            float p2 = fmaxf(f1 * e1v.z, f2 * e2v.z);
            float p3 = fmaxf(f1 * e1v.w, f2 * e2v.w);
            p0 = (av[p].x > 0) ? p0 : 0.f;
            p1 = (av[p].y > 0) ? p1 : 0.f;
            p2 = (av[p].z > 0) ? p2 : 0.f;
            p3 = (av[p].w > 0) ? p3 : 0.f;
            z[pbase + p] += (p0 + p1) + (p2 + p3);
            __half2 h01 = __floats2half2_rn(p0, p1);
            __half2 h23 = __floats2half2_rn(p2, p3);
            uint2 stv;
            stv.x = *reinterpret_cast<uint32_t*>(&h01);
            stv.y = *reinterpret_cast<uint32_t*>(&h23);
            *reinterpret_cast<uint2*>(pb + row * PS_STRIDE + jc) = stv;
        }
    };
    auto fillH_async = [&](int c, int buf) {
        const int j0 = jBase + c * BK;
        const uint32_t hb = hsBase + (uint32_t)(buf * HS_BUF * 2);
#pragma unroll
        for (int i = 0; i < 4; i++) {
            int idx = tid + i * 256;
            int r = idx >> 4;
            int g = idx & 15;
            cp_async16(hb + (uint32_t)(r * (HS_STRIDE * 2) + g * 16),
                       (const char*)(h16 + (size_t)(j0 + r) * F_OUT) + g * 16);
        }
    };
    auto mma2 = [&](int ktBase, int buf) {
        const uint32_t psB = aAddr0 + (uint32_t)(buf * PS_BUF * 2);
        const uint32_t hsB = hsBase + (uint32_t)(buf * HS_BUF * 2);
#pragma unroll
        for (int kt = ktBase; kt < ktBase + 2; kt++) {
            uint32_t afr[4];
            ldsm_x4(afr, psB + kt * 32);
            const uint32_t bRowAddr = hsB
                + (uint32_t)((kt * 16 + (lane & 15)) * (HS_STRIDE * 2))
                + (uint32_t)((lane >> 4) * 16);
#pragma unroll
            for (int np = 0; np < 8; np++) {
                uint32_t b[4];
                ldsm_x4_t(b, bRowAddr + np * 32);
                mma16816(acc[np * 2 + 0], afr, b[0], b[1]);
                mma16816(acc[np * 2 + 1], afr, b[2], b[3]);
            }
        }
    };

    __syncthreads();

    {
        fillH_async(0, 0);
        CP_COMMIT();
        const int j0 = jBase;
        float4 e1v = *(const float4*)&E1[j0 + jc];
        float4 e2v = *(const float4*)&E2[j0 + jc];
        int4 avA[4], avB[4];
        ldA4(avA, 0, 0);
        ldA4(avB, 4, 0);
        convP4(avA, 0, 0, e1v, e2v);
        convP4(avB, 4, 0, e1v, e2v);
        CP_WAIT0();
    }
    __syncthreads();

    for (int c = 0; c < NCHUNK; c++) {
        const int cb = c & 1;
        const int nb = cb ^ 1;
        const bool pre = (c + 1 < NCHUNK);
        float4 e1n, e2n;
        int4 avA[4], avB[4];
        if (pre) {
            fillH_async(c + 1, nb);
            CP_COMMIT();
            const int j0 = jBase + (c + 1) * BK;
            e1n = *(const float4*)&E1[j0 + jc];
            e2n = *(const float4*)&E2[j0 + jc];
            ldA4(avA, 0, c + 1);
        }
        mma2(0, cb);
        if (pre) {
            convP4(avA, 0, nb, e1n, e2n);
            ldA4(avB, 4, c + 1);
        }
        mma2(2, cb);
        if (pre) {
            convP4(avB, 4, nb, e1n, e2n);
            CP_WAIT0();
        }
        __syncthreads();
    }

#pragma unroll
    for (int p = 0; p < 8; p++) {
        float zz = z[p];
        zz += __shfl_xor_sync(0xffffffffu, zz, 1);
        zz += __shfl_xor_sync(0xffffffffu, zz, 2);
        zz += __shfl_xor_sync(0xffffffffu, zz, 4);
        zz += __shfl_xor_sync(0xffffffffu, zz, 8);
        if ((lane & 15) == 0)
            zp[kh * N_NODES + rowBase + wid * 16 + p * 2 + rsub] = zz;
    }

    float* partOut = part + (size_t)kh * N_NODES * F_OUT;
    const int r0 = rowBase + wid * 16 + (lane >> 2);
    const int c0 = (lane & 3) * 2;
#pragma unroll
    for (int nt = 0; nt < 16; nt++) {
        *(float2*)&partOut[(size_t)r0 * F_OUT + nt * 8 + c0] =
            make_float2(acc[nt][0], acc[nt][1]);
        *(float2*)&partOut[(size_t)(r0 + 8) * F_OUT + nt * 8 + c0] =
            make_float2(acc[nt][2], acc[nt][3]);
    }
}

// ---------------- kernel 3: out = sum(parts) / sum(z), 8 floats/thread -----
__global__ void __launch_bounds__(256) k_reduce(const float* __restrict__ part,
                                                const float* __restrict__ zp,
                                                float* __restrict__ out) {
    int base = (blockIdx.x * 256 + threadIdx.x) * 8;
    int row = base / F_OUT;
    float zs = 0.f;
#pragma unroll
    for (int q = 0; q < KSPLIT; q++) zs += zp[q * N_NODES + row];
    float zinv = 1.f / zs;
#pragma unroll
    for (int v = 0; v < 2; v++) {
        int i = base + v * 4;
        float4 acc = *(const float4*)&part[i];
#pragma unroll
        for (int q = 1; q < KSPLIT; q++) {
            float4 b = *(const float4*)&part[(size_t)q * N_NODES * F_OUT + i];
            acc.x += b.x; acc.y += b.y; acc.z += b.z; acc.w += b.w;
        }
        float4 o = make_float4(acc.x * zinv, acc.y * zinv, acc.z * zinv, acc.w * zinv);
        *(float4*)&out[i] = o;
    }
}

// ---------------- launch ----------------
extern "C" void kernel_launch(void* const* d_in, const int* in_sizes, int n_in,
                              void* d_out, int out_size) {
    const float* x   = (const float*)d_in[0];
    const int*   adj = (const int*)  d_in[1];
    const float* W   = (const float*)d_in[2];
    const float* a   = (const float*)d_in[3];
    float* out = (float*)d_out;

    float *F1, *F2, *E1, *E2, *part, *zp;
    __half* h16;
    cudaGetSymbolAddress((void**)&h16,  g_h16);
    cudaGetSymbolAddress((void**)&F1,   g_F1);
    cudaGetSymbolAddress((void**)&F2,   g_F2);
    cudaGetSymbolAddress((void**)&E1,   g_E1);
    cudaGetSymbolAddress((void**)&E2,   g_E2);
    cudaGetSymbolAddress((void**)&part, g_part);
    cudaGetSymbolAddress((void**)&zp,   g_zp);

    cudaFuncSetAttribute(k_gemm_h, cudaFuncAttributeMaxDynamicSharedMemorySize, SMEM_GH);
    cudaFuncSetAttribute(k_av_mma, cudaFuncAttributeMaxDynamicSharedMemorySize, SMEM_AV);

    k_gemm_h <<<N_NODES / GB_BM, 256, SMEM_GH>>>(x, W, a, h16, F1, F2, E1, E2);
    k_av_mma <<<(N_NODES / 128) * KSPLIT, 256, SMEM_AV>>>(adj, h16, F1, F2, E1, E2, part, zp);
    k_reduce <<<N_NODES * F_OUT / 2048, 256>>>(part, zp, out);
}